// round 5
// baseline (speedup 1.0000x reference)
#include <cuda_runtime.h>
#include <cstdint>
#include <cstddef>

// ---------------------------------------------------------------------------
// Problem constants
// ---------------------------------------------------------------------------
constexpr int B    = 4;
constexpr int CIN  = 128;
constexpr int NPT  = 1024;   // points
constexpr int KNN  = 9;
constexpr int MPT  = 4096;   // upsampled points = 4*N
constexpr int NCAND = 24;    // fp32 candidate shortlist size
constexpr float EPS_BN = 1e-5f;

// ---------------------------------------------------------------------------
// Scratch buffer (single __device__ global; offsets in floats)
// ---------------------------------------------------------------------------
constexpr size_t SZ_XN   = (size_t)B*CIN*NPT;      // 524288
constexpr size_t SZ_SQ   = (size_t)B*NPT;
constexpr size_t SZ_DOT  = (size_t)B*NPT*NPT;      // 4.19M
constexpr size_t SZ_W    = 256*128;
constexpr size_t SZ_UV   = (size_t)B*256*NPT;      // 1.05M
constexpr size_t SZ_D    = (size_t)B*256*(NPT*9);  // 9.44M
constexpr size_t SZ_PART = 256*B*2;
constexpr size_t SZ_NET  = (size_t)B*130*MPT;      // 2.13M
constexpr size_t SZ_P32  = (size_t)B*32*MPT;
constexpr size_t SZ_ROW  = (size_t)B*MPT;
constexpr size_t SZ_Y1   = (size_t)B*256*MPT;      // 4.19M

constexpr size_t O_XN    = 0;
constexpr size_t O_XNT   = O_XN   + SZ_XN;
constexpr size_t O_XTR   = O_XNT  + SZ_XN;   // raw x transposed (B,N,C)
constexpr size_t O_SQ    = O_XTR  + SZ_XN;
constexpr size_t O_DOT   = O_SQ   + SZ_SQ;
constexpr size_t O_W1A   = O_DOT  + SZ_DOT;
constexpr size_t O_W2A   = O_W1A  + SZ_W;
constexpr size_t O_W1B   = O_W2A  + SZ_W;
constexpr size_t O_W2B   = O_W1B  + SZ_W;
constexpr size_t O_UA    = O_W2B  + SZ_W;
constexpr size_t O_UB    = O_UA   + SZ_UV;
constexpr size_t O_D     = O_UB   + SZ_UV;   // shared between conv A and B
constexpr size_t O_MXA   = O_D    + SZ_D;
constexpr size_t O_MXB   = O_MXA  + SZ_UV;
constexpr size_t O_PARTA = O_MXB  + SZ_UV;
constexpr size_t O_PARTB = O_PARTA+ SZ_PART;
constexpr size_t O_AA    = O_PARTB+ SZ_PART;
constexpr size_t O_CA    = O_AA   + 256;
constexpr size_t O_AB2   = O_CA   + 256;
constexpr size_t O_CB2   = O_AB2  + 256;
constexpr size_t O_NET   = O_CB2  + 256;
constexpr size_t O_PF    = O_NET  + SZ_NET;
constexpr size_t O_PG    = O_PF   + SZ_P32;
constexpr size_t O_PH    = O_PG   + SZ_P32;
constexpr size_t O_F     = O_PH   + SZ_NET;
constexpr size_t O_G     = O_F    + SZ_P32;
constexpr size_t O_HN    = O_G    + SZ_P32;
constexpr size_t O_SCF   = O_HN   + SZ_NET;
constexpr size_t O_BIF   = O_SCF  + 32;
constexpr size_t O_SCG   = O_BIF  + 32;
constexpr size_t O_BIG   = O_SCG  + 32;
constexpr size_t O_SCH   = O_BIG  + 32;
constexpr size_t O_BIH   = O_SCH  + 130;
constexpr size_t O_RMAX  = O_BIH  + 130;
constexpr size_t O_RSUM  = O_RMAX + SZ_ROW;
constexpr size_t O_NET2  = O_RSUM + SZ_ROW;
constexpr size_t O_Y1    = O_NET2 + SZ_NET;
constexpr size_t O_END   = O_Y1   + SZ_Y1;

__device__ float  g_buf[O_END];
__device__ int    g_ibuf[(size_t)B*NPT*18];
__device__ int    g_cand[(size_t)B*NPT*NCAND];
__device__ double g_dbuf[(size_t)B*NPT*CIN + (size_t)B*NPT];   // xnd (b,n,c) + sqd

// ---------------------------------------------------------------------------
// 0. Weight prep: W1 = W[:, :128], W2 = W[:,128:] for both edge convs
// ---------------------------------------------------------------------------
__global__ void prep_w_kernel(const float* __restrict__ Wa, const float* __restrict__ Wb,
                              float* W1A, float* W2A, float* W1B, float* W2B) {
    int idx = blockIdx.x * 256 + threadIdx.x;
    if (idx >= 256 * 128) return;
    int o = idx >> 7, c = idx & 127;
    W1A[idx] = Wa[o*256 + c];       W2A[idx] = Wa[o*256 + 128 + c];
    W1B[idx] = Wb[o*256 + c];       W2B[idx] = Wb[o*256 + 128 + c];
}

// ---------------------------------------------------------------------------
// 1. Normalize in DOUBLE (true values): xn = x / max(||x||,1e-12).
//    Writes fp32 casts (xn, xnT) for the candidate GEMM, raw x^T for edge conv,
//    and double xnd/sqd for the exact refine step.
// ---------------------------------------------------------------------------
__global__ __launch_bounds__(256)
void normalize_kernel(const float* __restrict__ x,
                      float* __restrict__ xn, float* __restrict__ xnT,
                      float* __restrict__ xTr, float* __restrict__ sq,
                      double* __restrict__ xnd, double* __restrict__ sqd) {
    int t = blockIdx.x * 256 + threadIdx.x;
    if (t >= B * NPT) return;
    int b = t >> 10, n = t & 1023;
    const float* xp = x + (size_t)b * CIN * NPT + n;
    double ss = 0.0;
    #pragma unroll 8
    for (int c = 0; c < 128; c++) {
        double v = (double)xp[(size_t)c * NPT];
        ss += v * v;
    }
    double nrm = sqrt(ss);
    if (nrm < 1e-12) nrm = 1e-12;
    double inv = 1.0 / nrm;
    double s2 = 0.0;
    #pragma unroll 8
    for (int c = 0; c < 128; c++) {
        float vf = xp[(size_t)c * NPT];
        double xv = (double)vf * inv;
        xn[((size_t)b*CIN + c) * NPT + n] = (float)xv;
        xnT[((size_t)b*NPT + n) * CIN + c] = (float)xv;
        xTr[((size_t)b*NPT + n) * CIN + c] = vf;
        xnd[((size_t)b*NPT + n) * CIN + c] = xv;
        s2 += xv * xv;
    }
    sq[t] = (float)s2;
    sqd[(size_t)B*NPT*0 + t] = s2;   // sqd region starts right after xnd in g_dbuf
}

// ---------------------------------------------------------------------------
// 2. Generic tiled GEMM, sequential-k FMA chains:
//    C[b][m][n] = act( sum_k A[m][k]*X[b][k][n] + bias[m] )
// ---------------------------------------------------------------------------
__global__ __launch_bounds__(256)
void gemm_kernel(const float* __restrict__ A, size_t aStride,
                 const float* __restrict__ X, const float* __restrict__ bias,
                 float* __restrict__ C, int M, int K, int Nn, int doRelu) {
    __shared__ float As[32][33];
    __shared__ float Xs[32][65];
    int b = blockIdx.z;
    const float* Ab = A + (size_t)b * aStride;
    const float* Xb = X + (size_t)b * K * Nn;
    float* Cb = C + (size_t)b * M * Nn;
    int m0 = blockIdx.y * 32, n0 = blockIdx.x * 64;
    int tid = threadIdx.x, tx = tid & 31, ty = tid >> 5;
    float acc[4][2] = {};
    int kTiles = (K + 31) / 32;
    for (int kt = 0; kt < kTiles; kt++) {
        int k0 = kt * 32;
        for (int idx = tid; idx < 32*32; idx += 256) {
            int m = idx >> 5, k = idx & 31;
            float v = 0.f;
            if (m0 + m < M && k0 + k < K) v = Ab[(size_t)(m0+m)*K + k0 + k];
            As[k][m] = v;
        }
        for (int idx = tid; idx < 32*64; idx += 256) {
            int k = idx >> 6, n = idx & 63;
            float v = 0.f;
            if (k0 + k < K && n0 + n < Nn) v = Xb[(size_t)(k0+k)*Nn + n0 + n];
            Xs[k][n] = v;
        }
        __syncthreads();
        #pragma unroll
        for (int kk = 0; kk < 32; kk++) {
            float xv0 = Xs[kk][tx], xv1 = Xs[kk][tx + 32];
            #pragma unroll
            for (int mi = 0; mi < 4; mi++) {
                float av = As[kk][ty + mi*8];
                acc[mi][0] = __fmaf_rn(av, xv0, acc[mi][0]);
                acc[mi][1] = __fmaf_rn(av, xv1, acc[mi][1]);
            }
        }
        __syncthreads();
    }
    #pragma unroll
    for (int mi = 0; mi < 4; mi++) {
        int m = m0 + ty + mi*8;
        if (m >= M) continue;
        float bv = bias ? bias[m] : 0.f;
        #pragma unroll
        for (int ni = 0; ni < 2; ni++) {
            int n = n0 + tx + ni*32;
            if (n >= Nn) continue;
            float v = acc[mi][ni] + bv;
            if (doRelu) v = fmaxf(v, 0.f);
            Cb[(size_t)m*Nn + n] = v;
        }
    }
}

// ---------------------------------------------------------------------------
// 3a. Candidate top-24 per row from fp32 dist (set-accurate shortlist)
// ---------------------------------------------------------------------------
__global__ __launch_bounds__(256)
void topk_cand_kernel(const float* __restrict__ dot, const float* __restrict__ sq,
                      int* __restrict__ candout) {
    int bn = blockIdx.x;
    int b = bn >> 10;
    __shared__ float sc[1024];
    __shared__ float rv[256];
    __shared__ int   ri[256];
    int tid = threadIdx.x;
    const float* drow = dot + (size_t)bn * 1024;
    const float* sqb = sq + b * 1024;
    float sqn = sqb[bn & 1023];
    for (int m = tid; m < 1024; m += 256) {
        float t1 = __fadd_rn(sqn, -__fmul_rn(2.f, drow[m]));
        sc[m] = -__fadd_rn(t1, sqb[m]);
    }
    __syncthreads();
    for (int it = 0; it < NCAND; it++) {
        float bv = -INFINITY; int bi = 1 << 30;
        for (int m = tid; m < 1024; m += 256) {
            float v = sc[m];
            if (v > bv || (v == bv && m < bi)) { bv = v; bi = m; }
        }
        rv[tid] = bv; ri[tid] = bi;
        __syncthreads();
        for (int s = 128; s > 0; s >>= 1) {
            if (tid < s) {
                float v2 = rv[tid + s]; int i2 = ri[tid + s];
                if (v2 > rv[tid] || (v2 == rv[tid] && i2 < ri[tid])) { rv[tid] = v2; ri[tid] = i2; }
            }
            __syncthreads();
        }
        if (tid == 0) { candout[(size_t)bn*NCAND + it] = ri[0]; sc[ri[0]] = -INFINITY; }
        __syncthreads();
    }
}

// ---------------------------------------------------------------------------
// 3b. Refine: recompute candidate dists in double, round to fp32, sort with
//     jax's stable tie-break (value desc, index asc), emit top-18.
// ---------------------------------------------------------------------------
__global__ __launch_bounds__(128)
void refine_topk_kernel(const double* __restrict__ xnd, const double* __restrict__ sqd,
                        const int* __restrict__ cand, int* __restrict__ idxout) {
    int bn = blockIdx.x;
    int b = bn >> 10;
    int tid = threadIdx.x;
    __shared__ double xrow[128];
    __shared__ double red[128];
    __shared__ float  scores[NCAND];
    __shared__ int    cidx[NCAND];
    xrow[tid] = xnd[(size_t)bn * 128 + tid];
    if (tid < NCAND) cidx[tid] = cand[(size_t)bn*NCAND + tid];
    __syncthreads();
    double sqn = sqd[bn];
    for (int k = 0; k < NCAND; k++) {
        int m = cidx[k];
        red[tid] = xrow[tid] * xnd[((size_t)b*NPT + m) * 128 + tid];
        __syncthreads();
        #pragma unroll
        for (int s = 64; s > 0; s >>= 1) {
            if (tid < s) red[tid] += red[tid + s];
            __syncthreads();
        }
        if (tid == 0) {
            double dist = sqn - 2.0 * red[0] + sqd[(size_t)b*NPT + m];
            scores[k] = (float)(-dist);
        }
        __syncthreads();
    }
    if (tid == 0) {
        // insertion sort: score desc, index asc on ties
        for (int i = 1; i < NCAND; i++) {
            float sv = scores[i]; int iv = cidx[i];
            int j = i - 1;
            while (j >= 0 && (scores[j] < sv || (scores[j] == sv && cidx[j] > iv))) {
                scores[j+1] = scores[j]; cidx[j+1] = cidx[j];
                j--;
            }
            scores[j+1] = sv; cidx[j+1] = iv;
        }
        for (int r = 0; r < 18; r++) idxout[(size_t)bn*18 + r] = cidx[r];
    }
}

// ---------------------------------------------------------------------------
// 4. Edge gather-GEMM:  d[b][o][k*1024+n] = sum_c W2[o][c] *
//                                  ( x[c][idx[b,n,k*step]] - x[c][n] )
// ---------------------------------------------------------------------------
__global__ __launch_bounds__(256)
void edge_gemm_kernel(const float* __restrict__ W2, const float* __restrict__ xT,
                      const int* __restrict__ ibuf, int step,
                      float* __restrict__ dout) {
    __shared__ float As[32][33];
    __shared__ float Xs[32][65];
    __shared__ int js[64];
    int b = blockIdx.z;
    int m0 = blockIdx.y * 32, n0 = blockIdx.x * 64;
    int kk = n0 >> 10, nbase = n0 & 1023;
    int tid = threadIdx.x, tx = tid & 31, ty = tid >> 5;
    const float* xTb = xT + (size_t)b * NPT * CIN;
    float* Cb = dout + (size_t)b * 256 * 9216;
    if (tid < 64) js[tid] = ibuf[((size_t)b*NPT + nbase + tid)*18 + kk*step];
    __syncthreads();
    float acc[4][2] = {};
    #pragma unroll
    for (int kt = 0; kt < 4; kt++) {
        int k0 = kt * 32;
        for (int idx = tid; idx < 32*32; idx += 256) {
            int m = idx >> 5, k = idx & 31;
            As[k][m] = W2[(size_t)(m0+m)*128 + k0 + k];
        }
        for (int idx = tid; idx < 32*64; idx += 256) {
            int k = idx >> 6, n = idx & 63;
            int c = k0 + k;
            float xj = xTb[(size_t)js[n]*CIN + c];
            float xi = xTb[(size_t)(nbase+n)*CIN + c];
            Xs[k][n] = __fadd_rn(xj, -xi);
        }
        __syncthreads();
        #pragma unroll
        for (int kkk = 0; kkk < 32; kkk++) {
            float xv0 = Xs[kkk][tx], xv1 = Xs[kkk][tx + 32];
            #pragma unroll
            for (int mi = 0; mi < 4; mi++) {
                float av = As[kkk][ty + mi*8];
                acc[mi][0] = __fmaf_rn(av, xv0, acc[mi][0]);
                acc[mi][1] = __fmaf_rn(av, xv1, acc[mi][1]);
            }
        }
        __syncthreads();
    }
    #pragma unroll
    for (int mi = 0; mi < 4; mi++) {
        int m = m0 + ty + mi*8;
        #pragma unroll
        for (int ni = 0; ni < 2; ni++) {
            int n = n0 + tx + ni*32;
            Cb[(size_t)m*9216 + n] = acc[mi][ni];
        }
    }
}

// ---------------------------------------------------------------------------
// 5. Max over k and BN partial stats:  z = u + d;  Mx = max_k z; sums of z,z^2
// ---------------------------------------------------------------------------
__global__ __launch_bounds__(256)
void maxstats_kernel(const float* __restrict__ u, const float* __restrict__ d,
                     float* __restrict__ Mx, float* __restrict__ part) {
    int o = blockIdx.x, b = blockIdx.y;
    int tid = threadIdx.x;
    const float* ub = u + ((size_t)b*256 + o) * NPT;
    const float* db = d + ((size_t)b*256 + o) * 9216;
    float s1 = 0.f, s2 = 0.f;
    for (int n = tid; n < NPT; n += 256) {
        float uu = ub[n];
        float mx = -INFINITY;
        #pragma unroll
        for (int k = 0; k < 9; k++) {
            float z = uu + db[k*1024 + n];
            mx = fmaxf(mx, z);
            s1 += z; s2 += z * z;
        }
        Mx[((size_t)b*256 + o) * NPT + n] = mx;
    }
    __shared__ float r1[256], r2[256];
    r1[tid] = s1; r2[tid] = s2;
    __syncthreads();
    for (int s = 128; s > 0; s >>= 1) {
        if (tid < s) { r1[tid] += r1[tid+s]; r2[tid] += r2[tid+s]; }
        __syncthreads();
    }
    if (tid == 0) { part[(o*B + b)*2] = r1[0]; part[(o*B + b)*2 + 1] = r2[0]; }
}

__global__ void finalize_edge_kernel(const float* __restrict__ partA, const float* __restrict__ partB,
                                     const float* __restrict__ gA, const float* __restrict__ btA,
                                     const float* __restrict__ gB, const float* __restrict__ btB,
                                     float* aA, float* cA, float* aB, float* cB) {
    int t = threadIdx.x;
    const float invCnt = 1.f / (float)(B * NPT * KNN);
    if (t < 256) {
        float s1 = 0.f, s2 = 0.f;
        for (int b = 0; b < B; b++) { s1 += partA[(t*B+b)*2]; s2 += partA[(t*B+b)*2+1]; }
        float m = s1 * invCnt;
        float var = s2 * invCnt - m * m;
        float a = gA[t] * rsqrtf(var + EPS_BN);
        aA[t] = a; cA[t] = btA[t] - m * a;
    } else {
        int o = t - 256;
        float s1 = 0.f, s2 = 0.f;
        for (int b = 0; b < B; b++) { s1 += partB[(o*B+b)*2]; s2 += partB[(o*B+b)*2+1]; }
        float m = s1 * invCnt;
        float var = s2 * invCnt - m * m;
        float a = gB[o] * rsqrtf(var + EPS_BN);
        aB[o] = a; cB[o] = btB[o] - m * a;
    }
}

// ---------------------------------------------------------------------------
// 6. Build net (B,130,4096): reshape/concat/grid, fused relu(BN(max))
// ---------------------------------------------------------------------------
__global__ __launch_bounds__(256)
void build_net_kernel(const float* __restrict__ MxA, const float* __restrict__ MxB,
                      const float* __restrict__ aA, const float* __restrict__ cA,
                      const float* __restrict__ aB, const float* __restrict__ cB,
                      float* __restrict__ net) {
    int b = blockIdx.y;
    int m = blockIdx.x * 256 + threadIdx.x;
    int n = m >> 2, j = m & 3;
    float* np = net + (size_t)b * 130 * MPT;
    const float* MA = MxA + (size_t)b * 256 * NPT;
    const float* MB = MxB + (size_t)b * 256 * NPT;
    for (int c = 0; c < 128; c++) {
        float val;
        if (j < 2) {
            int o = j*128 + c;
            val = fmaxf(0.f, aA[o] * MA[(size_t)o*NPT + n] + cA[o]);
        } else {
            int o = (j-2)*128 + c;
            val = fmaxf(0.f, aB[o] * MB[(size_t)o*NPT + n] + cB[o]);
        }
        np[(size_t)c*MPT + m] = val;
    }
    int gq = m >> 10;
    np[(size_t)128*MPT + m] = (gq < 2) ? -0.2f : 0.2f;
    np[(size_t)129*MPT + m] = (gq & 1) ? 0.2f : -0.2f;
}

// ---------------------------------------------------------------------------
// 7. Attention BN stats (per channel over b,m) + normalize+relu
// ---------------------------------------------------------------------------
__global__ __launch_bounds__(256)
void stats_att_kernel(const float* __restrict__ P, int C,
                      const float* __restrict__ g, const float* __restrict__ be,
                      float* __restrict__ sc, float* __restrict__ bi) {
    int c = blockIdx.x;
    int tid = threadIdx.x;
    float s1 = 0.f, s2 = 0.f;
    for (int b = 0; b < B; b++) {
        const float* p = P + ((size_t)b*C + c) * MPT;
        for (int m = tid; m < MPT; m += 256) { float v = p[m]; s1 += v; s2 += v*v; }
    }
    __shared__ float r1[256], r2[256];
    r1[tid] = s1; r2[tid] = s2;
    __syncthreads();
    for (int s = 128; s > 0; s >>= 1) {
        if (tid < s) { r1[tid] += r1[tid+s]; r2[tid] += r2[tid+s]; }
        __syncthreads();
    }
    if (tid == 0) {
        const float invCnt = 1.f / (float)(B * MPT);
        float m = r1[0] * invCnt;
        float var = r2[0] * invCnt - m * m;
        float a = g[c] * rsqrtf(var + EPS_BN);
        sc[c] = a; bi[c] = be[c] - m * a;
    }
}

__global__ void norm_relu_kernel(const float* __restrict__ P,
                                 const float* __restrict__ sc, const float* __restrict__ bi,
                                 float* __restrict__ out, int C) {
    size_t idx = (size_t)blockIdx.x * 256 + threadIdx.x;
    size_t total = (size_t)B * C * MPT;
    if (idx >= total) return;
    int c = (int)((idx / MPT) % C);
    out[idx] = fmaxf(0.f, P[idx] * sc[c] + bi[c]);
}

// ---------------------------------------------------------------------------
// 8. Attention pass 1: per-row (n) online max & sum of exp over m
// ---------------------------------------------------------------------------
__global__ __launch_bounds__(256)
void att_pass1_kernel(const float* __restrict__ F, const float* __restrict__ G,
                      float* __restrict__ rmax, float* __restrict__ rsum) {
    int b = blockIdx.y;
    int n0 = blockIdx.x * 16;
    __shared__ float Gs[32][17];
    __shared__ float smx[16][256];
    __shared__ float ssm[16][256];
    int tid = threadIdx.x;
    for (int idx = tid; idx < 32*16; idx += 256) {
        int c = idx >> 4, r = idx & 15;
        Gs[c][r] = G[((size_t)b*32 + c) * MPT + n0 + r];
    }
    __syncthreads();
    float mx[16], sm[16];
    #pragma unroll
    for (int r = 0; r < 16; r++) { mx[r] = -INFINITY; sm[r] = 0.f; }
    for (int j = 0; j < 16; j++) {
        int m = tid + j * 256;
        float Fc[32];
        #pragma unroll
        for (int c = 0; c < 32; c++) Fc[c] = F[((size_t)b*32 + c) * MPT + m];
        #pragma unroll
        for (int r = 0; r < 16; r++) {
            float s = 0.f;
            #pragma unroll
            for (int c = 0; c < 32; c++) s = __fmaf_rn(Fc[c], Gs[c][r], s);
            if (s > mx[r]) { sm[r] = sm[r] * __expf(mx[r] - s) + 1.f; mx[r] = s; }
            else           { sm[r] += __expf(s - mx[r]); }
        }
    }
    #pragma unroll
    for (int r = 0; r < 16; r++) { smx[r][tid] = mx[r]; ssm[r][tid] = sm[r]; }
    __syncthreads();
    int w = tid >> 5, lane = tid & 31;
    for (int rr = w; rr < 16; rr += 8) {
        float M = -INFINITY, S = 0.f;
        for (int e = lane; e < 256; e += 32) {
            float m2 = smx[rr][e], s2 = ssm[rr][e];
            if (m2 > M) { S = S * __expf(M - m2) + s2; M = m2; }
            else        { S += s2 * __expf(m2 - M); }
        }
        #pragma unroll
        for (int o = 16; o > 0; o >>= 1) {
            float m2 = __shfl_xor_sync(0xffffffffu, M, o);
            float s2 = __shfl_xor_sync(0xffffffffu, S, o);
            if (m2 > M) { S = S * __expf(M - m2) + s2; M = m2; }
            else        { S += s2 * __expf(m2 - M); }
        }
        if (lane == 0) {
            rmax[(size_t)b*MPT + n0 + rr] = M;
            rsum[(size_t)b*MPT + n0 + rr] = S;
        }
    }
}

// ---------------------------------------------------------------------------
// 9. Attention pass 2: o[c,m] = sum_n H[c,n] * beta[n,m];
//    beta = exp(s - rowmax) / S.  Fused net2 = gamma*o + net.
// ---------------------------------------------------------------------------
constexpr int P2_SMEM = (32*129 + 32*129 + 132*33 + 32*33 + 64) * 4;

__global__ __launch_bounds__(256)
void att_pass2_kernel(const float* __restrict__ F, const float* __restrict__ G,
                      const float* __restrict__ Hn,
                      const float* __restrict__ rmax, const float* __restrict__ rsum,
                      const float* __restrict__ net, const float* __restrict__ gamma,
                      float* __restrict__ net2) {
    extern __shared__ float dyn[];
    float* Fs  = dyn;                    // [32][129]
    float* es  = Fs  + 32*129;           // [32][129]
    float* Hs  = es  + 32*129;           // [132][33]  (c-major)
    float* Gs  = Hs  + 132*33;           // [32][33]
    float* rmx = Gs  + 32*33;            // [32]
    float* rsm = rmx + 32;               // [32]

    int b = blockIdx.y;
    int m0 = blockIdx.x * 128;
    int tid = threadIdx.x;
    for (int idx = tid; idx < 32*128; idx += 256) {
        int c = idx >> 7, mm = idx & 127;
        Fs[c*129 + mm] = F[((size_t)b*32 + c) * MPT + m0 + mm];
    }
    int cg = tid >> 6, ml = tid & 63;
    int cb = cg * 33;
    int nc = (cg < 3) ? 33 : 31;
    float acc[33][2];
    #pragma unroll
    for (int i = 0; i < 33; i++) { acc[i][0] = 0.f; acc[i][1] = 0.f; }
    int nl = tid & 31, mg = tid >> 5;

    for (int nt = 0; nt < 128; nt++) {
        int n0v = nt * 32;
        if (tid < 32) {
            rmx[tid] = rmax[(size_t)b*MPT + n0v + tid];
            rsm[tid] = rsum[(size_t)b*MPT + n0v + tid];
        }
        for (int idx = tid; idx < 32*32; idx += 256) {
            int c = idx >> 5, jj = idx & 31;
            Gs[c*33 + jj] = G[((size_t)b*32 + c) * MPT + n0v + jj];
        }
        for (int idx = tid; idx < 130*32; idx += 256) {
            int c = idx >> 5, jj = idx & 31;
            Hs[c*33 + jj] = Hn[((size_t)b*130 + c) * MPT + n0v + jj];
        }
        __syncthreads();
        {
            float gc[32];
            #pragma unroll
            for (int c = 0; c < 32; c++) gc[c] = Gs[c*33 + nl];
            float rm = rmx[nl], rs = rsm[nl];
            #pragma unroll
            for (int q = 0; q < 16; q++) {
                int mm = mg * 16 + q;
                float s = 0.f;
                #pragma unroll
                for (int c = 0; c < 32; c++) s = __fmaf_rn(gc[c], Fs[c*129 + mm], s);
                es[nl*129 + mm] = __fdiv_rn(__expf(s - rm), rs);
            }
        }
        __syncthreads();
        for (int j = 0; j < 32; j++) {
            float e0 = es[j*129 + ml], e1 = es[j*129 + ml + 64];
            #pragma unroll
            for (int i = 0; i < 33; i++) {
                float h = Hs[(cb + i)*33 + j];
                acc[i][0] = __fmaf_rn(h, e0, acc[i][0]);
                acc[i][1] = __fmaf_rn(h, e1, acc[i][1]);
            }
        }
        __syncthreads();
    }
    float gm = gamma[0];
    for (int i = 0; i < nc; i++) {
        int c = cb + i;
        size_t off = ((size_t)b*130 + c) * MPT + m0;
        net2[off + ml]      = gm * acc[i][0] + net[off + ml];
        net2[off + ml + 64] = gm * acc[i][1] + net[off + ml + 64];
    }
}

// ---------------------------------------------------------------------------
// Host launch
// ---------------------------------------------------------------------------
extern "C" void kernel_launch(void* const* d_in, const int* in_sizes, int n_in,
                              void* d_out, int out_size) {
    float* buf = nullptr; int* ibuf = nullptr; int* candb = nullptr; double* dbuf = nullptr;
    cudaGetSymbolAddress((void**)&buf,   g_buf);
    cudaGetSymbolAddress((void**)&ibuf,  g_ibuf);
    cudaGetSymbolAddress((void**)&candb, g_cand);
    cudaGetSymbolAddress((void**)&dbuf,  g_dbuf);
    cudaFuncSetAttribute(att_pass2_kernel, cudaFuncAttributeMaxDynamicSharedMemorySize, P2_SMEM);

    const float* inp  = (const float*)d_in[0];
    const float* Wa   = (const float*)d_in[1];
    const float* gna  = (const float*)d_in[2];
    const float* bta  = (const float*)d_in[3];
    const float* Wb   = (const float*)d_in[4];
    const float* gnb  = (const float*)d_in[5];
    const float* btb  = (const float*)d_in[6];
    const float* Wf   = (const float*)d_in[7];
    const float* gf   = (const float*)d_in[9];
    const float* bef  = (const float*)d_in[10];
    const float* Wg   = (const float*)d_in[11];
    const float* gg   = (const float*)d_in[13];
    const float* beg  = (const float*)d_in[14];
    const float* Wh   = (const float*)d_in[15];
    const float* gh   = (const float*)d_in[17];
    const float* beh  = (const float*)d_in[18];
    const float* gamma= (const float*)d_in[19];
    const float* W1   = (const float*)d_in[20];
    const float* b1   = (const float*)d_in[21];
    const float* W2   = (const float*)d_in[22];
    const float* b2   = (const float*)d_in[23];
    float* out = (float*)d_out;

    float *xn   = buf + O_XN,   *xnT  = buf + O_XNT, *xTr = buf + O_XTR, *sq = buf + O_SQ;
    float *dot  = buf + O_DOT;
    float *W1A  = buf + O_W1A,  *W2A  = buf + O_W2A, *W1B = buf + O_W1B, *W2B = buf + O_W2B;
    float *uA   = buf + O_UA,   *uB   = buf + O_UB,  *dEd = buf + O_D;
    float *MxA  = buf + O_MXA,  *MxB  = buf + O_MXB;
    float *partA= buf + O_PARTA,*partB= buf + O_PARTB;
    float *aA   = buf + O_AA,   *cA   = buf + O_CA,  *aB  = buf + O_AB2, *cB = buf + O_CB2;
    float *net  = buf + O_NET;
    float *Pf   = buf + O_PF,   *Pg   = buf + O_PG,  *Ph  = buf + O_PH;
    float *Fb   = buf + O_F,    *Gb   = buf + O_G,   *HnB = buf + O_HN;
    float *scf  = buf + O_SCF,  *bif  = buf + O_BIF, *scg = buf + O_SCG, *big = buf + O_BIG;
    float *sch  = buf + O_SCH,  *bih  = buf + O_BIH;
    float *rmax = buf + O_RMAX, *rsum = buf + O_RSUM;
    float *net2 = buf + O_NET2, *y1   = buf + O_Y1;
    double *xnd = dbuf;
    double *sqd = dbuf + (size_t)B*NPT*CIN;

    // 0. weight prep
    prep_w_kernel<<<128, 256>>>(Wa, Wb, W1A, W2A, W1B, W2B);
    // 1. normalize (double-accurate)
    normalize_kernel<<<(B*NPT)/256, 256>>>(inp, xn, xnT, xTr, sq, xnd, sqd);
    // 2. fp32 dot matrix (candidate shortlist quality only)
    gemm_kernel<<<dim3(NPT/64, NPT/32, B), 256>>>(xnT, (size_t)NPT*CIN, xn, nullptr, dot, NPT, CIN, NPT, 0);
    // 3. candidate top-24, then exact double refine -> top-18
    topk_cand_kernel<<<B*NPT, 256>>>(dot, sq, candb);
    refine_topk_kernel<<<B*NPT, 128>>>(xnd, sqd, candb, ibuf);
    // 4. u = W1 * x_i
    gemm_kernel<<<dim3(NPT/64, 8, B), 256>>>(W1A, 0, inp, nullptr, uA, 256, CIN, NPT, 0);
    gemm_kernel<<<dim3(NPT/64, 8, B), 256>>>(W1B, 0, inp, nullptr, uB, 256, CIN, NPT, 0);
    // 5. conv A: d = W2A * (x_j - x_i), then max+stats
    edge_gemm_kernel<<<dim3(9216/64, 8, B), 256>>>(W2A, xTr, ibuf, 1, dEd);
    maxstats_kernel<<<dim3(256, B), 256>>>(uA, dEd, MxA, partA);
    // 6. conv B (dilation 2), reusing d buffer
    edge_gemm_kernel<<<dim3(9216/64, 8, B), 256>>>(W2B, xTr, ibuf, 2, dEd);
    maxstats_kernel<<<dim3(256, B), 256>>>(uB, dEd, MxB, partB);
    finalize_edge_kernel<<<1, 512>>>(partA, partB, gna, bta, gnb, btb, aA, cA, aB, cB);
    // 7. build net (B,130,4096)
    build_net_kernel<<<dim3(MPT/256, B), 256>>>(MxA, MxB, aA, cA, aB, cB, net);
    // 8. attention projections (biases no-op under BN)
    gemm_kernel<<<dim3(MPT/64, 1, B), 256>>>(Wf, 0, net, nullptr, Pf, 32, 130, MPT, 0);
    gemm_kernel<<<dim3(MPT/64, 1, B), 256>>>(Wg, 0, net, nullptr, Pg, 32, 130, MPT, 0);
    gemm_kernel<<<dim3(MPT/64, 5, B), 256>>>(Wh, 0, net, nullptr, Ph, 130, 130, MPT, 0);
    // 9. attention BN
    stats_att_kernel<<<32, 256>>>(Pf, 32, gf, bef, scf, bif);
    stats_att_kernel<<<32, 256>>>(Pg, 32, gg, beg, scg, big);
    stats_att_kernel<<<130, 256>>>(Ph, 130, gh, beh, sch, bih);
    norm_relu_kernel<<<(unsigned)((B*32*MPT + 255)/256), 256>>>(Pf, scf, bif, Fb, 32);
    norm_relu_kernel<<<(unsigned)((B*32*MPT + 255)/256), 256>>>(Pg, scg, big, Gb, 32);
    norm_relu_kernel<<<(unsigned)((B*130*MPT + 255)/256), 256>>>(Ph, sch, bih, HnB, 130);
    // 10. softmax stats + attention output (fused residual)
    att_pass1_kernel<<<dim3(MPT/16, B), 256>>>(Fb, Gb, rmax, rsum);
    att_pass2_kernel<<<dim3(MPT/128, B), 256, P2_SMEM>>>(Fb, Gb, HnB, rmax, rsum, net, gamma, net2);
    // 11. final 1x1 convs
    gemm_kernel<<<dim3(MPT/64, 8, B), 256>>>(W1, 0, net2, b1, y1, 256, 130, MPT, 1);
    gemm_kernel<<<dim3(MPT/64, 4, B), 256>>>(W2, 0, y1, b2, out, 128, 256, MPT, 1);
}

// round 6
// speedup vs baseline: 1.4234x; 1.4234x over previous
#include <cuda_runtime.h>
#include <cstdint>
#include <cstddef>

// ---------------------------------------------------------------------------
// Problem constants
// ---------------------------------------------------------------------------
constexpr int B    = 4;
constexpr int CIN  = 128;
constexpr int NPT  = 1024;   // points
constexpr int KNN  = 9;
constexpr int MPT  = 4096;   // upsampled points = 4*N
constexpr int NCAND = 24;    // fp32 candidate shortlist size
constexpr float EPS_BN = 1e-5f;

// ---------------------------------------------------------------------------
// f32x2 packed-FMA helpers (Blackwell FFMA2)
// ---------------------------------------------------------------------------
using u64 = unsigned long long;
__device__ __forceinline__ u64 dup2(float v) {
    u64 r; asm("mov.b64 %0, {%1, %1};" : "=l"(r) : "f"(v)); return r;
}
__device__ __forceinline__ u64 fma2(u64 a, u64 b, u64 c) {
    u64 d; asm("fma.rn.f32x2 %0, %1, %2, %3;" : "=l"(d) : "l"(a), "l"(b), "l"(c)); return d;
}
__device__ __forceinline__ void unpack2(u64 v, float& lo, float& hi) {
    asm("mov.b64 {%0, %1}, %2;" : "=f"(lo), "=f"(hi) : "l"(v));
}

// ---------------------------------------------------------------------------
// Scratch buffer (single __device__ global; offsets in floats)
// ---------------------------------------------------------------------------
constexpr size_t SZ_XN   = (size_t)B*CIN*NPT;      // 524288
constexpr size_t SZ_SQ   = (size_t)B*NPT;
constexpr size_t SZ_DOT  = (size_t)B*NPT*NPT;      // 4.19M
constexpr size_t SZ_W    = 256*128;
constexpr size_t SZ_UV   = (size_t)B*256*NPT;      // 1.05M
constexpr size_t SZ_PART = 256*64*2;               // per-o, 64 (b,nblk) slots, {s1,s2}
constexpr size_t SZ_NET  = (size_t)B*130*MPT;      // 2.13M
constexpr size_t SZ_P32  = (size_t)B*32*MPT;
constexpr size_t SZ_ROW  = (size_t)B*MPT;
constexpr size_t SZ_Y1   = (size_t)B*256*MPT;      // 4.19M

constexpr size_t O_XN    = 0;
constexpr size_t O_XNT   = O_XN   + SZ_XN;
constexpr size_t O_XTR   = O_XNT  + SZ_XN;   // raw x transposed (B,N,C)
constexpr size_t O_SQ    = O_XTR  + SZ_XN;
constexpr size_t O_DOT   = O_SQ   + SZ_SQ;
constexpr size_t O_W1A   = O_DOT  + SZ_DOT;
constexpr size_t O_W2A   = O_W1A  + SZ_W;
constexpr size_t O_W1B   = O_W2A  + SZ_W;
constexpr size_t O_W2B   = O_W1B  + SZ_W;
constexpr size_t O_UA    = O_W2B  + SZ_W;
constexpr size_t O_UB    = O_UA   + SZ_UV;
constexpr size_t O_MXA   = O_UB   + SZ_UV;
constexpr size_t O_MXB   = O_MXA  + SZ_UV;
constexpr size_t O_PARTA = O_MXB  + SZ_UV;
constexpr size_t O_PARTB = O_PARTA+ SZ_PART;
constexpr size_t O_AA    = O_PARTB+ SZ_PART;
constexpr size_t O_CA    = O_AA   + 256;
constexpr size_t O_AB2   = O_CA   + 256;
constexpr size_t O_CB2   = O_AB2  + 256;
constexpr size_t O_NET   = O_CB2  + 256;
constexpr size_t O_PF    = O_NET  + SZ_NET;
constexpr size_t O_PG    = O_PF   + SZ_P32;
constexpr size_t O_PH    = O_PG   + SZ_P32;
constexpr size_t O_F     = O_PH   + SZ_NET;
constexpr size_t O_G     = O_F    + SZ_P32;
constexpr size_t O_HN    = O_G    + SZ_P32;
constexpr size_t O_SCF   = O_HN   + SZ_NET;
constexpr size_t O_BIF   = O_SCF  + 32;
constexpr size_t O_SCG   = O_BIF  + 32;
constexpr size_t O_BIG   = O_SCG  + 32;
constexpr size_t O_SCH   = O_BIG  + 32;
constexpr size_t O_BIH   = O_SCH  + 130;
constexpr size_t O_RMAX  = O_BIH  + 130;
constexpr size_t O_RINV  = O_RMAX + SZ_ROW;
constexpr size_t O_NET2  = O_RINV + SZ_ROW;
constexpr size_t O_Y1    = O_NET2 + SZ_NET;
constexpr size_t O_END   = O_Y1   + SZ_Y1;

__device__ float  g_buf[O_END];
__device__ int    g_ibuf[(size_t)B*NPT*18];
__device__ int    g_cand[(size_t)B*NPT*NCAND];
__device__ double g_dbuf[(size_t)B*NPT*CIN + (size_t)B*NPT];   // xnd (b,n,c) + sqd

// ---------------------------------------------------------------------------
// 0. Weight prep: W1 = W[:, :128], W2 = W[:,128:] for both edge convs
// ---------------------------------------------------------------------------
__global__ void prep_w_kernel(const float* __restrict__ Wa, const float* __restrict__ Wb,
                              float* W1A, float* W2A, float* W1B, float* W2B) {
    int idx = blockIdx.x * 256 + threadIdx.x;
    if (idx >= 256 * 128) return;
    int o = idx >> 7, c = idx & 127;
    W1A[idx] = Wa[o*256 + c];       W2A[idx] = Wa[o*256 + 128 + c];
    W1B[idx] = Wb[o*256 + c];       W2B[idx] = Wb[o*256 + 128 + c];
}

// ---------------------------------------------------------------------------
// 1. Normalize in DOUBLE (true values).
// ---------------------------------------------------------------------------
__global__ __launch_bounds__(256)
void normalize_kernel(const float* __restrict__ x,
                      float* __restrict__ xn, float* __restrict__ xnT,
                      float* __restrict__ xTr, float* __restrict__ sq,
                      double* __restrict__ xnd, double* __restrict__ sqd) {
    int t = blockIdx.x * 256 + threadIdx.x;
    if (t >= B * NPT) return;
    int b = t >> 10, n = t & 1023;
    const float* xp = x + (size_t)b * CIN * NPT + n;
    double ss = 0.0;
    #pragma unroll 8
    for (int c = 0; c < 128; c++) {
        double v = (double)xp[(size_t)c * NPT];
        ss += v * v;
    }
    double nrm = sqrt(ss);
    if (nrm < 1e-12) nrm = 1e-12;
    double inv = 1.0 / nrm;
    double s2 = 0.0;
    #pragma unroll 8
    for (int c = 0; c < 128; c++) {
        float vf = xp[(size_t)c * NPT];
        double xv = (double)vf * inv;
        xn[((size_t)b*CIN + c) * NPT + n] = (float)xv;
        xnT[((size_t)b*NPT + n) * CIN + c] = (float)xv;
        xTr[((size_t)b*NPT + n) * CIN + c] = vf;
        xnd[((size_t)b*NPT + n) * CIN + c] = xv;
        s2 += xv * xv;
    }
    sq[t] = (float)s2;
    sqd[t] = s2;
}

// ---------------------------------------------------------------------------
// 2. Tiled GEMM, f32x2 (two independent n-columns per FMA2 — bit-identical
//    to scalar sequential-k):  C[b][m][n] = act( A@X + bias )
// ---------------------------------------------------------------------------
__global__ __launch_bounds__(256)
void gemm_kernel(const float* __restrict__ A, size_t aStride,
                 const float* __restrict__ X, const float* __restrict__ bias,
                 float* __restrict__ C, int M, int K, int Nn, int doRelu) {
    __shared__ u64   As2[32][33];   // [k][m], duplicated pairs
    __shared__ float Xs[32][66];
    int b = blockIdx.z;
    const float* Ab = A + (size_t)b * aStride;
    const float* Xb = X + (size_t)b * K * Nn;
    float* Cb = C + (size_t)b * M * Nn;
    int m0 = blockIdx.y * 32, n0 = blockIdx.x * 64;
    int tid = threadIdx.x, tx = tid & 31, ty = tid >> 5;
    u64 acc2[4] = {0, 0, 0, 0};
    int kTiles = (K + 31) / 32;
    for (int kt = 0; kt < kTiles; kt++) {
        int k0 = kt * 32;
        for (int idx = tid; idx < 32*32; idx += 256) {
            int m = idx >> 5, k = idx & 31;
            float v = 0.f;
            if (m0 + m < M && k0 + k < K) v = Ab[(size_t)(m0+m)*K + k0 + k];
            As2[k][m] = dup2(v);
        }
        for (int idx = tid; idx < 32*64; idx += 256) {
            int k = idx >> 6, n = idx & 63;
            float v = 0.f;
            if (k0 + k < K && n0 + n < Nn) v = Xb[(size_t)(k0+k)*Nn + n0 + n];
            Xs[k][n] = v;
        }
        __syncthreads();
        #pragma unroll
        for (int kk = 0; kk < 32; kk++) {
            u64 xv2 = *reinterpret_cast<const u64*>(&Xs[kk][2*tx]);
            #pragma unroll
            for (int mi = 0; mi < 4; mi++)
                acc2[mi] = fma2(As2[kk][ty + mi*8], xv2, acc2[mi]);
        }
        __syncthreads();
    }
    #pragma unroll
    for (int mi = 0; mi < 4; mi++) {
        int m = m0 + ty + mi*8;
        if (m >= M) continue;
        float bv = bias ? bias[m] : 0.f;
        float v0, v1; unpack2(acc2[mi], v0, v1);
        v0 += bv; v1 += bv;
        if (doRelu) { v0 = fmaxf(v0, 0.f); v1 = fmaxf(v1, 0.f); }
        int n = n0 + 2*tx;
        Cb[(size_t)m*Nn + n]     = v0;
        Cb[(size_t)m*Nn + n + 1] = v1;
    }
}

// ---------------------------------------------------------------------------
// 3a. Candidate top-24, warp-per-row, register-resident (no barriers)
// ---------------------------------------------------------------------------
__global__ __launch_bounds__(256)
void topk_cand_kernel(const float* __restrict__ dot, const float* __restrict__ sq,
                      int* __restrict__ candout) {
    int warp = threadIdx.x >> 5, lane = threadIdx.x & 31;
    int bn = blockIdx.x * 8 + warp;
    int b = bn >> 10;
    const float* drow = dot + (size_t)bn * 1024;
    const float* sqb = sq + b * 1024;
    float sqn = sqb[bn & 1023];
    float val[32];
    #pragma unroll
    for (int q = 0; q < 32; q++) {
        int m = q * 32 + lane;
        float t1 = __fadd_rn(sqn, -__fmul_rn(2.f, drow[m]));
        val[q] = -__fadd_rn(t1, sqb[m]);
    }
    float bv = val[0]; int bq = 0;
    #pragma unroll
    for (int q = 1; q < 32; q++) if (val[q] > bv) { bv = val[q]; bq = q; }
    for (int it = 0; it < NCAND; it++) {
        float v = bv; int bi = bq * 32 + lane;
        #pragma unroll
        for (int off = 16; off > 0; off >>= 1) {
            float v2 = __shfl_xor_sync(0xffffffffu, v, off);
            int   i2 = __shfl_xor_sync(0xffffffffu, bi, off);
            if (v2 > v || (v2 == v && i2 < bi)) { v = v2; bi = i2; }
        }
        if (lane == 0) candout[(size_t)bn*NCAND + it] = bi;
        if ((bi & 31) == lane) {
            int qs = bi >> 5;
            #pragma unroll
            for (int q = 0; q < 32; q++) if (q == qs) val[q] = -INFINITY;
            bv = val[0]; bq = 0;
            #pragma unroll
            for (int q = 1; q < 32; q++) if (val[q] > bv) { bv = val[q]; bq = q; }
        }
    }
}

// ---------------------------------------------------------------------------
// 3b. Refine: exact double dists for 24 candidates (warp-per-candidate),
//     round to fp32, stable sort (value desc, index asc), emit top-18.
// ---------------------------------------------------------------------------
__global__ __launch_bounds__(128)
void refine_topk_kernel(const double* __restrict__ xnd, const double* __restrict__ sqd,
                        const int* __restrict__ cand, int* __restrict__ idxout) {
    int bn = blockIdx.x;
    int b = bn >> 10;
    int tid = threadIdx.x, lane = tid & 31, warp = tid >> 5;
    __shared__ float scores[NCAND];
    __shared__ int   cidx[NCAND];
    if (tid < NCAND) cidx[tid] = cand[(size_t)bn*NCAND + tid];
    const double* xrp = xnd + (size_t)bn * 128 + lane * 4;
    double xr0 = xrp[0], xr1 = xrp[1], xr2 = xrp[2], xr3 = xrp[3];
    __syncthreads();
    double sqn = sqd[bn];
    for (int k = warp; k < NCAND; k += 4) {
        int m = cidx[k];
        const double* xm = xnd + ((size_t)b*NPT + m) * 128 + lane * 4;
        double s = xr0*xm[0] + xr1*xm[1] + xr2*xm[2] + xr3*xm[3];
        #pragma unroll
        for (int off = 16; off > 0; off >>= 1)
            s += __shfl_xor_sync(0xffffffffu, s, off);
        if (lane == 0)
            scores[k] = (float)(-(sqn - 2.0 * s + sqd[(size_t)b*NPT + m]));
    }
    __syncthreads();
    if (tid == 0) {
        float sc[NCAND]; int ci[NCAND];
        for (int i = 0; i < NCAND; i++) { sc[i] = scores[i]; ci[i] = cidx[i]; }
        for (int i = 1; i < NCAND; i++) {
            float sv = sc[i]; int iv = ci[i];
            int j = i - 1;
            while (j >= 0 && (sc[j] < sv || (sc[j] == sv && ci[j] > iv))) {
                sc[j+1] = sc[j]; ci[j+1] = ci[j]; j--;
            }
            sc[j+1] = sv; ci[j+1] = iv;
        }
        for (int r = 0; r < 18; r++) idxout[(size_t)bn*18 + r] = ci[r];
    }
}

// ---------------------------------------------------------------------------
// 4. FUSED edge conv: gather(coalesced) + W2@(xj-xi) + u + max_k + BN stats.
//    FMA order per output identical to the R5 split kernels.
// ---------------------------------------------------------------------------
__global__ __launch_bounds__(256)
void edge_fused_kernel(const float* __restrict__ W2, const float* __restrict__ u,
                       const float* __restrict__ xT, const int* __restrict__ ibuf,
                       int step, float* __restrict__ Mx, float* __restrict__ part) {
    __shared__ u64   W2s2[128][33];   // [k][m] duplicated
    __shared__ float Xs[32][66];
    __shared__ int   js[64];
    int b = blockIdx.z, bx = blockIdx.x;
    int m0 = blockIdx.y * 32, n0 = bx * 64;
    int tid = threadIdx.x, tx = tid & 31, ty = tid >> 5;
    const float* xTb = xT + (size_t)b * NPT * CIN;

    for (int idx = tid; idx < 32*128; idx += 256) {
        int m = idx >> 7, k = idx & 127;
        W2s2[k][m] = dup2(W2[(size_t)(m0+m)*128 + k]);
    }
    float2 u2[4];
    #pragma unroll
    for (int mi = 0; mi < 4; mi++)
        u2[mi] = *reinterpret_cast<const float2*>(
            &u[((size_t)b*256 + m0 + ty + mi*8)*NPT + n0 + 2*tx]);

    float mx0[4], mx1[4], s1[4], s2s[4];
    #pragma unroll
    for (int mi = 0; mi < 4; mi++) { mx0[mi] = -INFINITY; mx1[mi] = -INFINITY; s1[mi] = 0.f; s2s[mi] = 0.f; }
    __syncthreads();

    for (int k = 0; k < 9; k++) {
        if (tid < 64) js[tid] = ibuf[((size_t)b*NPT + n0 + tid)*18 + k*step];
        __syncthreads();
        u64 acc2[4] = {0, 0, 0, 0};
        #pragma unroll
        for (int ct = 0; ct < 4; ct++) {
            #pragma unroll
            for (int p = 0; p < 8; p++) {
                int nl = (tid >> 5) + p*8;
                int cl = tid & 31;
                int c = ct*32 + cl;
                float xj = xTb[(size_t)js[nl]*128 + c];
                float xi = xTb[(size_t)(n0 + nl)*128 + c];
                Xs[cl][nl] = __fadd_rn(xj, -xi);
            }
            __syncthreads();
            #pragma unroll
            for (int kk = 0; kk < 32; kk++) {
                u64 xv2 = *reinterpret_cast<const u64*>(&Xs[kk][2*tx]);
                #pragma unroll
                for (int mi = 0; mi < 4; mi++)
                    acc2[mi] = fma2(W2s2[ct*32 + kk][ty + mi*8], xv2, acc2[mi]);
            }
            __syncthreads();
        }
        #pragma unroll
        for (int mi = 0; mi < 4; mi++) {
            float d0, d1; unpack2(acc2[mi], d0, d1);
            float z0 = u2[mi].x + d0, z1 = u2[mi].y + d1;
            mx0[mi] = fmaxf(mx0[mi], z0); mx1[mi] = fmaxf(mx1[mi], z1);
            s1[mi]  += z0 + z1;
            s2s[mi] += z0*z0 + z1*z1;
        }
    }
    #pragma unroll
    for (int mi = 0; mi < 4; mi++) {
        size_t off = ((size_t)b*256 + m0 + ty + mi*8)*NPT + n0 + 2*tx;
        Mx[off] = mx0[mi]; Mx[off + 1] = mx1[mi];
    }
    #pragma unroll
    for (int mi = 0; mi < 4; mi++) {
        float a = s1[mi], c2 = s2s[mi];
        #pragma unroll
        for (int off = 16; off > 0; off >>= 1) {
            a  += __shfl_xor_sync(0xffffffffu, a, off);
            c2 += __shfl_xor_sync(0xffffffffu, c2, off);
        }
        if (tx == 0) {
            int o = m0 + ty + mi*8;
            int slot = b*16 + bx;
            part[((size_t)o*64 + slot)*2]     = a;
            part[((size_t)o*64 + slot)*2 + 1] = c2;
        }
    }
}

__global__ void finalize_edge_kernel(const float* __restrict__ partA, const float* __restrict__ partB,
                                     const float* __restrict__ gA, const float* __restrict__ btA,
                                     const float* __restrict__ gB, const float* __restrict__ btB,
                                     float* aA, float* cA, float* aB, float* cB) {
    int t = threadIdx.x;
    const float invCnt = 1.f / (float)(B * NPT * KNN);
    if (t < 256) {
        float s1 = 0.f, s2 = 0.f;
        for (int j = 0; j < 64; j++) { s1 += partA[((size_t)t*64 + j)*2]; s2 += partA[((size_t)t*64 + j)*2 + 1]; }
        float m = s1 * invCnt;
        float var = s2 * invCnt - m * m;
        float a = gA[t] * rsqrtf(var + EPS_BN);
        aA[t] = a; cA[t] = btA[t] - m * a;
    } else {
        int o = t - 256;
        float s1 = 0.f, s2 = 0.f;
        for (int j = 0; j < 64; j++) { s1 += partB[((size_t)o*64 + j)*2]; s2 += partB[((size_t)o*64 + j)*2 + 1]; }
        float m = s1 * invCnt;
        float var = s2 * invCnt - m * m;
        float a = gB[o] * rsqrtf(var + EPS_BN);
        aB[o] = a; cB[o] = btB[o] - m * a;
    }
}

// ---------------------------------------------------------------------------
// 6. Build net (B,130,4096)
// ---------------------------------------------------------------------------
__global__ __launch_bounds__(256)
void build_net_kernel(const float* __restrict__ MxA, const float* __restrict__ MxB,
                      const float* __restrict__ aA, const float* __restrict__ cA,
                      const float* __restrict__ aB, const float* __restrict__ cB,
                      float* __restrict__ net) {
    int b = blockIdx.y;
    int m = blockIdx.x * 256 + threadIdx.x;
    int n = m >> 2, j = m & 3;
    float* np = net + (size_t)b * 130 * MPT;
    const float* MA = MxA + (size_t)b * 256 * NPT;
    const float* MB = MxB + (size_t)b * 256 * NPT;
    for (int c = 0; c < 128; c++) {
        float val;
        if (j < 2) {
            int o = j*128 + c;
            val = fmaxf(0.f, aA[o] * MA[(size_t)o*NPT + n] + cA[o]);
        } else {
            int o = (j-2)*128 + c;
            val = fmaxf(0.f, aB[o] * MB[(size_t)o*NPT + n] + cB[o]);
        }
        np[(size_t)c*MPT + m] = val;
    }
    int gq = m >> 10;
    np[(size_t)128*MPT + m] = (gq < 2) ? -0.2f : 0.2f;
    np[(size_t)129*MPT + m] = (gq & 1) ? 0.2f : -0.2f;
}

// ---------------------------------------------------------------------------
// 7. Attention BN stats + normalize+relu
// ---------------------------------------------------------------------------
__global__ __launch_bounds__(256)
void stats_att_kernel(const float* __restrict__ P, int C,
                      const float* __restrict__ g, const float* __restrict__ be,
                      float* __restrict__ sc, float* __restrict__ bi) {
    int c = blockIdx.x;
    int tid = threadIdx.x;
    float s1 = 0.f, s2 = 0.f;
    for (int b = 0; b < B; b++) {
        const float* p = P + ((size_t)b*C + c) * MPT;
        for (int m = tid; m < MPT; m += 256) { float v = p[m]; s1 += v; s2 += v*v; }
    }
    __shared__ float r1[256], r2[256];
    r1[tid] = s1; r2[tid] = s2;
    __syncthreads();
    for (int s = 128; s > 0; s >>= 1) {
        if (tid < s) { r1[tid] += r1[tid+s]; r2[tid] += r2[tid+s]; }
        __syncthreads();
    }
    if (tid == 0) {
        const float invCnt = 1.f / (float)(B * MPT);
        float m = r1[0] * invCnt;
        float var = r2[0] * invCnt - m * m;
        float a = g[c] * rsqrtf(var + EPS_BN);
        sc[c] = a; bi[c] = be[c] - m * a;
    }
}

__global__ void norm_relu_kernel(const float* __restrict__ P,
                                 const float* __restrict__ sc, const float* __restrict__ bi,
                                 float* __restrict__ out, int C) {
    size_t idx = (size_t)blockIdx.x * 256 + threadIdx.x;
    size_t total = (size_t)B * C * MPT;
    if (idx >= total) return;
    int c = (int)((idx / MPT) % C);
    out[idx] = fmaxf(0.f, P[idx] * sc[c] + bi[c]);
}

// ---------------------------------------------------------------------------
// 8. Attention pass 1: per-row max & sum of exp (f32x2 pairwise-c dot),
//    stores rmax and rinv = 1/S.
// ---------------------------------------------------------------------------
__global__ __launch_bounds__(256)
void att_pass1_kernel(const float* __restrict__ F, const float* __restrict__ G,
                      float* __restrict__ rmax, float* __restrict__ rinv) {
    int b = blockIdx.y;
    int n0 = blockIdx.x * 16;
    __shared__ u64 Gs2[16][17];
    __shared__ float smx[16][256];
    __shared__ float ssm[16][256];
    int tid = threadIdx.x;
    {
        int cp = tid >> 4, r = tid & 15;
        float g0 = G[((size_t)b*32 + 2*cp) * MPT + n0 + r];
        float g1 = G[((size_t)b*32 + 2*cp + 1) * MPT + n0 + r];
        u64 p; asm("mov.b64 %0, {%1, %2};" : "=l"(p) : "f"(g0), "f"(g1));
        Gs2[cp][r] = p;
    }
    __syncthreads();
    float mx[16], sm[16];
    #pragma unroll
    for (int r = 0; r < 16; r++) { mx[r] = -INFINITY; sm[r] = 0.f; }
    for (int j = 0; j < 16; j++) {
        int m = tid + j * 256;
        u64 fp2[16];
        #pragma unroll
        for (int cp = 0; cp < 16; cp++) {
            float f0 = F[((size_t)b*32 + 2*cp) * MPT + m];
            float f1 = F[((size_t)b*32 + 2*cp + 1) * MPT + m];
            asm("mov.b64 %0, {%1, %2};" : "=l"(fp2[cp]) : "f"(f0), "f"(f1));
        }
        #pragma unroll
        for (int r = 0; r < 16; r++) {
            u64 sacc = 0;
            #pragma unroll
            for (int cp = 0; cp < 16; cp++) sacc = fma2(fp2[cp], Gs2[cp][r], sacc);
            float s0, s1v; unpack2(sacc, s0, s1v);
            float s = s0 + s1v;
            if (s > mx[r]) { sm[r] = sm[r] * __expf(mx[r] - s) + 1.f; mx[r] = s; }
            else           { sm[r] += __expf(s - mx[r]); }
        }
    }
    #pragma unroll
    for (int r = 0; r < 16; r++) { smx[r][tid] = mx[r]; ssm[r][tid] = sm[r]; }
    __syncthreads();
    int w = tid >> 5, lane = tid & 31;
    for (int rr = w; rr < 16; rr += 8) {
        float M = -INFINITY, S = 0.f;
        for (int e = lane; e < 256; e += 32) {
            float m2 = smx[rr][e], s2 = ssm[rr][e];
            if (m2 > M) { S = S * __expf(M - m2) + s2; M = m2; }
            else        { S += s2 * __expf(m2 - M); }
        }
        #pragma unroll
        for (int o = 16; o > 0; o >>= 1) {
            float m2 = __shfl_xor_sync(0xffffffffu, M, o);
            float s2 = __shfl_xor_sync(0xffffffffu, S, o);
            if (m2 > M) { S = S * __expf(M - m2) + s2; M = m2; }
            else        { S += s2 * __expf(m2 - M); }
        }
        if (lane == 0) {
            rmax[(size_t)b*MPT + n0 + rr] = M;
            rinv[(size_t)b*MPT + n0 + rr] = __fdiv_rn(1.f, S);
        }
    }
}

// ---------------------------------------------------------------------------
// 9. Attention pass 2 (f32x2): warp owns 17 channels, lane owns 4 m.
//    o[c,m] = sum_n (H[c,n]*rinv_n) * exp(s[n,m]-rmax_n); net2 = gamma*o + net.
// ---------------------------------------------------------------------------
constexpr int P2_SMEM = 136*33*8 + 32*130*4 + 32*130*4 + 32*33*4 + 32*4;

__global__ __launch_bounds__(256, 1)
void att_pass2_kernel(const float* __restrict__ F, const float* __restrict__ G,
                      const float* __restrict__ Hn,
                      const float* __restrict__ rmax, const float* __restrict__ rinv,
                      const float* __restrict__ net, const float* __restrict__ gamma,
                      float* __restrict__ net2) {
    extern __shared__ char smem_raw[];
    u64*   Hs2 = reinterpret_cast<u64*>(smem_raw);       // [136][33] dup(h*rinv)
    float* Fs  = reinterpret_cast<float*>(Hs2 + 136*33); // [32][130]
    float* es  = Fs + 32*130;                            // [32][130]
    float* Gs  = es + 32*130;                            // [32][33]
    float* rmx = Gs + 32*33;                             // [32]

    int b = blockIdx.y;
    int m0 = blockIdx.x * 128;
    int tid = threadIdx.x;
    int w = tid >> 5, lane = tid & 31;
    int c0 = w * 17;

    for (int idx = tid; idx < 32*128; idx += 256) {
        int c = idx >> 7, mm = idx & 127;
        Fs[c*130 + mm] = F[((size_t)b*32 + c) * MPT + m0 + mm];
    }
    u64 acc2[17][2];
    #pragma unroll
    for (int i = 0; i < 17; i++) { acc2[i][0] = 0; acc2[i][1] = 0; }

    for (int nt = 0; nt < 128; nt++) {
        int n0v = nt * 32;
        __syncthreads();
        if (tid < 32) rmx[tid] = rmax[(size_t)b*MPT + n0v + tid];
        for (int idx = tid; idx < 32*32; idx += 256) {
            int c = idx >> 5, jj = idx & 31;
            Gs[c*33 + jj] = G[((size_t)b*32 + c) * MPT + n0v + jj];
        }
        for (int idx = tid; idx < 136*32; idx += 256) {
            int c = idx >> 5, jj = idx & 31;
            float h = 0.f;
            if (c < 130)
                h = Hn[((size_t)b*130 + c) * MPT + n0v + jj] * rinv[(size_t)b*MPT + n0v + jj];
            Hs2[c*33 + jj] = dup2(h);
        }
        __syncthreads();
        // s-phase: thread (nl = lane-role, mg) computes 16 m as 8 pairs
        {
            int nl = tid & 31, mg = tid >> 5;
            float gc[32];
            #pragma unroll
            for (int c = 0; c < 32; c++) gc[c] = Gs[c*33 + nl];
            float rm = rmx[nl];
            #pragma unroll
            for (int q = 0; q < 8; q++) {
                int mm = mg*16 + 2*q;
                u64 sacc = 0;
                #pragma unroll
                for (int c = 0; c < 32; c++)
                    sacc = fma2(dup2(gc[c]), *reinterpret_cast<const u64*>(&Fs[c*130 + mm]), sacc);
                float s0, s1v; unpack2(sacc, s0, s1v);
                es[nl*130 + mm]     = __expf(s0 - rm);
                es[nl*130 + mm + 1] = __expf(s1v - rm);
            }
        }
        __syncthreads();
        // o-phase
        #pragma unroll 4
        for (int j = 0; j < 32; j++) {
            u64 e01 = *reinterpret_cast<const u64*>(&es[j*130 + 4*lane]);
            u64 e23 = *reinterpret_cast<const u64*>(&es[j*130 + 4*lane + 2]);
            #pragma unroll
            for (int i = 0; i < 17; i++) {
                u64 h2 = Hs2[(c0 + i)*33 + j];
                acc2[i][0] = fma2(h2, e01, acc2[i][0]);
                acc2[i][1] = fma2(h2, e23, acc2[i][1]);
            }
        }
    }
    float gm = gamma[0];
    #pragma unroll
    for (int i = 0; i < 17; i++) {
        int c = c0 + i;
        if (c >= 130) break;
        size_t off = ((size_t)b*130 + c) * MPT + m0 + 4*lane;
        float a0, a1, a2, a3;
        unpack2(acc2[i][0], a0, a1);
        unpack2(acc2[i][1], a2, a3);
        net2[off]     = gm * a0 + net[off];
        net2[off + 1] = gm * a1 + net[off + 1];
        net2[off + 2] = gm * a2 + net[off + 2];
        net2[off + 3] = gm * a3 + net[off + 3];
    }
}

// ---------------------------------------------------------------------------
// Host launch
// ---------------------------------------------------------------------------
extern "C" void kernel_launch(void* const* d_in, const int* in_sizes, int n_in,
                              void* d_out, int out_size) {
    float* buf = nullptr; int* ibuf = nullptr; int* candb = nullptr; double* dbuf = nullptr;
    cudaGetSymbolAddress((void**)&buf,   g_buf);
    cudaGetSymbolAddress((void**)&ibuf,  g_ibuf);
    cudaGetSymbolAddress((void**)&candb, g_cand);
    cudaGetSymbolAddress((void**)&dbuf,  g_dbuf);
    cudaFuncSetAttribute(att_pass2_kernel, cudaFuncAttributeMaxDynamicSharedMemorySize, P2_SMEM);

    const float* inp  = (const float*)d_in[0];
    const float* Wa   = (const float*)d_in[1];
    const float* gna  = (const float*)d_in[2];
    const float* bta  = (const float*)d_in[3];
    const float* Wb   = (const float*)d_in[4];
    const float* gnb  = (const float*)d_in[5];
    const float* btb  = (const float*)d_in[6];
    const float* Wf   = (const float*)d_in[7];
    const float* gf   = (const float*)d_in[9];
    const float* bef  = (const float*)d_in[10];
    const float* Wg   = (const float*)d_in[11];
    const float* gg   = (const float*)d_in[13];
    const float* beg  = (const float*)d_in[14];
    const float* Wh   = (const float*)d_in[15];
    const float* gh   = (const float*)d_in[17];
    const float* beh  = (const float*)d_in[18];
    const float* gamma= (const float*)d_in[19];
    const float* W1   = (const float*)d_in[20];
    const float* b1   = (const float*)d_in[21];
    const float* W2   = (const float*)d_in[22];
    const float* b2   = (const float*)d_in[23];
    float* out = (float*)d_out;

    float *xn   = buf + O_XN,   *xnT  = buf + O_XNT, *xTr = buf + O_XTR, *sq = buf + O_SQ;
    float *dot  = buf + O_DOT;
    float *W1A  = buf + O_W1A,  *W2A  = buf + O_W2A, *W1B = buf + O_W1B, *W2B = buf + O_W2B;
    float *uA   = buf + O_UA,   *uB   = buf + O_UB;
    float *MxA  = buf + O_MXA,  *MxB  = buf + O_MXB;
    float *partA= buf + O_PARTA,*partB= buf + O_PARTB;
    float *aA   = buf + O_AA,   *cA   = buf + O_CA,  *aB  = buf + O_AB2, *cB = buf + O_CB2;
    float *net  = buf + O_NET;
    float *Pf   = buf + O_PF,   *Pg   = buf + O_PG,  *Ph  = buf + O_PH;
    float *Fb   = buf + O_F,    *Gb   = buf + O_G,   *HnB = buf + O_HN;
    float *scf  = buf + O_SCF,  *bif  = buf + O_BIF, *scg = buf + O_SCG, *big = buf + O_BIG;
    float *sch  = buf + O_SCH,  *bih  = buf + O_BIH;
    float *rmax = buf + O_RMAX, *rinv = buf + O_RINV;
    float *net2 = buf + O_NET2, *y1   = buf + O_Y1;
    double *xnd = dbuf;
    double *sqd = dbuf + (size_t)B*NPT*CIN;

    // 0. weight prep
    prep_w_kernel<<<128, 256>>>(Wa, Wb, W1A, W2A, W1B, W2B);
    // 1. normalize (double-accurate)
    normalize_kernel<<<(B*NPT)/256, 256>>>(inp, xn, xnT, xTr, sq, xnd, sqd);
    // 2. fp32 dot matrix (shortlist only)
    gemm_kernel<<<dim3(NPT/64, NPT/32, B), 256>>>(xnT, (size_t)NPT*CIN, xn, nullptr, dot, NPT, CIN, NPT, 0);
    // 3. candidate top-24 (warp-per-row), exact double refine -> top-18
    topk_cand_kernel<<<(B*NPT)/8, 256>>>(dot, sq, candb);
    refine_topk_kernel<<<B*NPT, 128>>>(xnd, sqd, candb, ibuf);
    // 4. u = W1 * x_i
    gemm_kernel<<<dim3(NPT/64, 8, B), 256>>>(W1A, 0, inp, nullptr, uA, 256, CIN, NPT, 0);
    gemm_kernel<<<dim3(NPT/64, 8, B), 256>>>(W1B, 0, inp, nullptr, uB, 256, CIN, NPT, 0);
    // 5. fused edge convs (gather + GEMM + max + stats)
    edge_fused_kernel<<<dim3(16, 8, B), 256>>>(W2A, uA, xTr, ibuf, 1, MxA, partA);
    edge_fused_kernel<<<dim3(16, 8, B), 256>>>(W2B, uB, xTr, ibuf, 2, MxB, partB);
    finalize_edge_kernel<<<1, 512>>>(partA, partB, gna, bta, gnb, btb, aA, cA, aB, cB);
    // 6. build net (B,130,4096)
    build_net_kernel<<<dim3(MPT/256, B), 256>>>(MxA, MxB, aA, cA, aB, cB, net);
    // 7. attention projections
    gemm_kernel<<<dim3(MPT/64, 1, B), 256>>>(Wf, 0, net, nullptr, Pf, 32, 130, MPT, 0);
    gemm_kernel<<<dim3(MPT/64, 1, B), 256>>>(Wg, 0, net, nullptr, Pg, 32, 130, MPT, 0);
    gemm_kernel<<<dim3(MPT/64, 5, B), 256>>>(Wh, 0, net, nullptr, Ph, 130, 130, MPT, 0);
    // 8. attention BN
    stats_att_kernel<<<32, 256>>>(Pf, 32, gf, bef, scf, bif);
    stats_att_kernel<<<32, 256>>>(Pg, 32, gg, beg, scg, big);
    stats_att_kernel<<<130, 256>>>(Ph, 130, gh, beh, sch, bih);
    norm_relu_kernel<<<(unsigned)((B*32*MPT + 255)/256), 256>>>(Pf, scf, bif, Fb, 32);
    norm_relu_kernel<<<(unsigned)((B*32*MPT + 255)/256), 256>>>(Pg, scg, big, Gb, 32);
    norm_relu_kernel<<<(unsigned)((B*130*MPT + 255)/256), 256>>>(Ph, sch, bih, HnB, 130);
    // 9. softmax stats + attention output (fused residual)
    att_pass1_kernel<<<dim3(MPT/16, B), 256>>>(Fb, Gb, rmax, rinv);
    att_pass2_kernel<<<dim3(MPT/128, B), 256, P2_SMEM>>>(Fb, Gb, HnB, rmax, rinv, net, gamma, net2);
    // 10. final 1x1 convs
    gemm_kernel<<<dim3(MPT/64, 8, B), 256>>>(W1, 0, net2, b1, y1, 256, 130, MPT, 1);
    gemm_kernel<<<dim3(MPT/64, 4, B), 256>>>(W2, 0, y1, b2, out, 128, 256, MPT, 1);
}